// round 16
// baseline (speedup 1.0000x reference)
#include <cuda_runtime.h>
#include <cuda_fp16.h>
#include <cstdint>
#include <math.h>

// Problem dims (fixed)
#define H_DIM 4096
#define I_DIM 11008
#define NTOK  4096
#define I_HALF 5504                     // K split for down (86 * 64)

#define BKH 64                          // halves (k) per pipeline stage
#define S  4
#define LDSTR 72                        // halves per smem row (128B data + 16B pad)
#define TILE128 (128 * LDSTR)
#define NTHREADS 512
#define NCTA 148                        // <= SM count; 1 CTA/SM via smem -> all co-resident

#define STG_F (3 * TILE128)             // fused stage: A + Bu + Bg
#define STG_D (2 * TILE128)             // down stage: A + B
#define SMEM_BYTES (S * STG_F * 2)      // 221184

// Work pool 1 layout
#define N_GATHER 32
#define N_CVTW   (86 * 8)               // wu+wg cvt, 8 chunks (16 rows) per n-block
#define N_FUSED  (86 * 32)              // n-major
#define N_CVTD   128                    // wd cvt, 32 rows each
#define N_ZERO   64                     // zero out, 64 rows each
#define ID_CVTW  (N_GATHER)
#define ID_FUSED (ID_CVTW + N_CVTW)     // 720
#define ID_CVTD  (ID_FUSED + N_FUSED)   // 3472
#define ID_ZERO  (ID_CVTD + N_CVTD)     // 3600
#define TOTAL1   (ID_ZERO + N_ZERO)     // 3664
// Pool 2: down tiles, m(32) x n(32) x k(2); m slowest for A-tile L2 reuse
#define TOTAL2   (32 * 32 * 2)

// Device scratch — natural K-major fp16 layouts
__device__ __half g_x[(size_t)NTOK * H_DIM];
__device__ __half g_h[(size_t)NTOK * I_DIM];
__device__ __half g_wu[(size_t)I_DIM * H_DIM];
__device__ __half g_wg[(size_t)I_DIM * H_DIM];
__device__ __half g_wd[(size_t)H_DIM * I_DIM];
__device__ int    g_idx[NTOK];
__device__ int    g_zidx[NTOK];
__device__ int    g_count;

// Control block (zeroed by cudaMemsetAsync each launch)
struct Ctl {
    int ctr1, ctr2, bar;
    int wcnt[86];
    int wflag[86];
    int gflag[32];
};
__device__ Ctl g_ctl;

// ---------------------------------------------------------------------------
__device__ __forceinline__ uint32_t h2_as_u32(__half2 h) {
    return *reinterpret_cast<uint32_t*>(&h);
}
__device__ __forceinline__ void cp16(void* dst_smem, const void* src) {
    uint32_t d = (uint32_t)__cvta_generic_to_shared(dst_smem);
    asm volatile("cp.async.cg.shared.global [%0], [%1], 16;" :: "r"(d), "l"(src) : "memory");
}
#define CP_COMMIT() asm volatile("cp.async.commit_group;" ::: "memory")
#define CP_WAIT(n)  asm volatile("cp.async.wait_group %0;" :: "n"(n) : "memory")

__device__ __forceinline__ void mma16(float* d, const uint32_t* a, const uint32_t* b) {
    asm volatile(
        "mma.sync.aligned.m16n8k16.row.col.f32.f16.f16.f32 "
        "{%0,%1,%2,%3}, {%4,%5,%6,%7}, {%8,%9}, {%0,%1,%2,%3};"
        : "+f"(d[0]), "+f"(d[1]), "+f"(d[2]), "+f"(d[3])
        : "r"(a[0]), "r"(a[1]), "r"(a[2]), "r"(a[3]), "r"(b[0]), "r"(b[1]));
}
__device__ __forceinline__ void ldsm4(uint32_t addr, uint32_t* r) {
    asm volatile("ldmatrix.sync.aligned.m8n8.x4.shared.b16 {%0,%1,%2,%3}, [%4];"
                 : "=r"(r[0]), "=r"(r[1]), "=r"(r[2]), "=r"(r[3]) : "r"(addr));
}
__device__ __forceinline__ uint4 cvt8(float4 f0, float4 f1) {
    uint4 o;
    o.x = h2_as_u32(__floats2half2_rn(f0.x, f0.y));
    o.y = h2_as_u32(__floats2half2_rn(f0.z, f0.w));
    o.z = h2_as_u32(__floats2half2_rn(f1.x, f1.y));
    o.w = h2_as_u32(__floats2half2_rn(f1.z, f1.w));
    return o;
}
__device__ __forceinline__ void spin_flag(volatile int* f) { while (*f == 0) {} }

// ---------------------------------------------------------------------------
// Compaction scan (single block): active list + inactive list
// ---------------------------------------------------------------------------
__global__ void compact_kernel(const int* __restrict__ mask) {
    __shared__ int warp_sums[32];
    const int tid = threadIdx.x, lane = tid & 31, warp = tid >> 5;
    int flags[4], cnt = 0;
#pragma unroll
    for (int j = 0; j < 4; ++j) {
        int f = (mask[tid * 4 + j] != 0) ? 1 : 0;
        flags[j] = f; cnt += f;
    }
    int v = cnt;
#pragma unroll
    for (int o = 1; o < 32; o <<= 1) { int n = __shfl_up_sync(~0u, v, o); if (lane >= o) v += n; }
    if (lane == 31) warp_sums[warp] = v;
    __syncthreads();
    if (warp == 0) {
        int s = warp_sums[lane];
#pragma unroll
        for (int o = 1; o < 32; o <<= 1) { int n = __shfl_up_sync(~0u, s, o); if (lane >= o) s += n; }
        warp_sums[lane] = s;
    }
    __syncthreads();
    int base = v - cnt + (warp > 0 ? warp_sums[warp - 1] : 0);
#pragma unroll
    for (int j = 0; j < 4; ++j) {
        int t = tid * 4 + j;
        if (flags[j]) g_idx[base++] = t;
        else          g_zidx[t - base] = t;
    }
    if (tid == 1023) g_count = base;
}

// ---------------------------------------------------------------------------
// Pool item bodies (noinline keeps register allocation predictable)
// ---------------------------------------------------------------------------
__device__ __noinline__ void gather_item(int m, const float4* __restrict__ hidden) {
    const int tid = threadIdx.x;
    const int c = g_count;
    const int m0 = m * 128;
    uint4* dst = (uint4*)(g_x + (size_t)m0 * H_DIM);
    if (m0 < ((c + 127) & ~127)) {
        for (int i = tid; i < 128 * 512; i += NTHREADS) {
            const int r = i >> 9, ch = i & 511;
            const int row = m0 + r;
            if (row < c) {
                const float4* src = hidden + (size_t)g_idx[row] * (H_DIM / 4) + 2 * ch;
                dst[(size_t)r * 512 + ch] = cvt8(src[0], src[1]);
            } else {
                dst[(size_t)r * 512 + ch] = make_uint4(0, 0, 0, 0);
            }
        }
    }
    __syncthreads();
    __threadfence();
    if (tid == 0) atomicExch(&g_ctl.gflag[m], 1);
}

__device__ __noinline__ void cvtw_item(int id2, const float4* __restrict__ w_up,
                                       const float4* __restrict__ w_gate) {
    const int tid = threadIdx.x;
    const int n = id2 >> 3, chunk = id2 & 7;
    const size_t row0 = (size_t)n * 128 + chunk * 16;      // 16 rows of both mats
    const size_t e_off = row0 * H_DIM;
    const float4* su = w_up   + e_off / 4;
    const float4* sg = w_gate + e_off / 4;
    uint4* du = (uint4*)(g_wu + e_off);
    uint4* dg = (uint4*)(g_wg + e_off);
    const int ng = 16 * H_DIM / 8;                          // 8192 groups
    for (int i = tid; i < ng; i += NTHREADS) du[i] = cvt8(su[2 * i], su[2 * i + 1]);
    for (int i = tid; i < ng; i += NTHREADS) dg[i] = cvt8(sg[2 * i], sg[2 * i + 1]);
    __syncthreads();
    __threadfence();
    if (tid == 0) {
        if (atomicAdd(&g_ctl.wcnt[n], 1) == 7) atomicExch(&g_ctl.wflag[n], 1);
    }
}

__device__ __noinline__ void cvtd_item(int id2, const float4* __restrict__ w_down) {
    const int tid = threadIdx.x;
    const size_t e_off = (size_t)id2 * 32 * I_DIM;          // 32 rows
    const float4* s = w_down + e_off / 4;
    uint4* d = (uint4*)(g_wd + e_off);
    const int ng = 32 * I_DIM / 8;                          // 44032 groups
    for (int i = tid; i < ng; i += NTHREADS) d[i] = cvt8(s[2 * i], s[2 * i + 1]);
}

__device__ __noinline__ void zero_item(int id2, float* __restrict__ out) {
    const int tid = threadIdx.x;
    float4* p = (float4*)(out + (size_t)id2 * 64 * H_DIM);
    float4 z = make_float4(0.f, 0.f, 0.f, 0.f);
    const int n4 = 64 * H_DIM / 4;                          // 65536
    for (int i = tid; i < n4; i += NTHREADS) p[i] = z;
}

// ---------------------------------------------------------------------------
// Fused up+gate tile: 128x128, 16 warps @ 32x32 (4m x 4n), dual acc, kg skew.
// ---------------------------------------------------------------------------
__device__ __noinline__ void fused_item(int fid) {
    const int Mc = g_count;
    const int n = fid >> 5, m = fid & 31;
    const int m0 = m * 128;
    if (m0 >= Mc) return;
    const int n0 = n * 128;
    const int tid = threadIdx.x;

    if (tid == 0) { spin_flag(&g_ctl.gflag[m]); spin_flag(&g_ctl.wflag[n]); }
    __syncthreads();
    __threadfence();

    extern __shared__ __half smh[];
    const uint32_t smem_b = (uint32_t)__cvta_generic_to_shared(smh);

    const int lane = tid & 31;
    const int wid  = tid >> 5;
    const int wm   = wid >> 2;
    const int wn   = wid & 3;
    const int g    = lane >> 2;
    const int c    = lane & 3;
    const int skew = wid & 3;
    const int nk   = H_DIM / BKH;   // 64

    uint32_t a_off[2], u_off[2], gg_off[2];
    {
        const int ar = wm * 32 + ((lane >> 3) & 1) * 8 + (lane & 7);
        const int ac = ((lane >> 4) & 1) * 8;
#pragma unroll
        for (int i = 0; i < 2; ++i) a_off[i] = (uint32_t)((ar + i * 16) * LDSTR + ac);
        const int br = wn * 32 + ((lane >> 4) & 1) * 8 + (lane & 7);
        const int bc = ((lane >> 3) & 1) * 8;
#pragma unroll
        for (int p = 0; p < 2; ++p) {
            u_off[p]  = (uint32_t)(TILE128     + (br + p * 16) * LDSTR + bc);
            gg_off[p] = (uint32_t)(2 * TILE128 + (br + p * 16) * LDSTR + bc);
        }
    }

    const __half* srcA = g_x  + (size_t)m0 * H_DIM;
    const __half* srcU = g_wu + (size_t)n0 * H_DIM;
    const __half* srcG = g_wg + (size_t)n0 * H_DIM;

#define ISSUE_F(t) do {                                                        \
        __half* st = smh + ((t) % S) * STG_F;                                  \
        const size_t kof = (size_t)(t) * BKH;                                  \
        _Pragma("unroll")                                                      \
        for (int ii = 0; ii < 2; ++ii) {                                       \
            int id = tid + ii * 512;                                           \
            int row = id >> 3, ch = id & 7;                                    \
            cp16(st + row * LDSTR + ch * 8,                                    \
                 srcA + (size_t)row * H_DIM + kof + ch * 8);                   \
            cp16(st + TILE128 + row * LDSTR + ch * 8,                          \
                 srcU + (size_t)row * H_DIM + kof + ch * 8);                   \
            cp16(st + 2 * TILE128 + row * LDSTR + ch * 8,                      \
                 srcG + (size_t)row * H_DIM + kof + ch * 8);                   \
        }                                                                      \
    } while (0)

#pragma unroll
    for (int t = 0; t < S - 1; ++t) { ISSUE_F(t); CP_COMMIT(); }

    float acc_u[2][4][4], acc_g[2][4][4];
#pragma unroll
    for (int i = 0; i < 2; ++i)
#pragma unroll
        for (int j = 0; j < 4; ++j)
#pragma unroll
            for (int r = 0; r < 4; ++r) { acc_u[i][j][r] = 0.f; acc_g[i][j][r] = 0.f; }

    for (int t = 0; t < nk; ++t) {
        CP_WAIT(S - 2);
        __syncthreads();
        if (t + S - 1 < nk) ISSUE_F(t + S - 1);
        CP_COMMIT();

        const uint32_t sb = smem_b + (uint32_t)((t % S) * STG_F) * 2;

#pragma unroll
        for (int kgi = 0; kgi < 4; ++kgi) {
            const int kg = (kgi + skew) & 3;
            const uint32_t kb = (uint32_t)kg * 32;
            uint32_t af[2][4], uf[4][2], gf[4][2];
#pragma unroll
            for (int i = 0; i < 2; ++i) ldsm4(sb + 2 * a_off[i] + kb, af[i]);
#pragma unroll
            for (int p = 0; p < 2; ++p) {
                uint32_t ru[4], rg[4];
                ldsm4(sb + 2 * u_off[p] + kb, ru);
                ldsm4(sb + 2 * gg_off[p] + kb, rg);
                uf[2 * p][0] = ru[0]; uf[2 * p][1] = ru[1];
                uf[2 * p + 1][0] = ru[2]; uf[2 * p + 1][1] = ru[3];
                gf[2 * p][0] = rg[0]; gf[2 * p][1] = rg[1];
                gf[2 * p + 1][0] = rg[2]; gf[2 * p + 1][1] = rg[3];
            }
#pragma unroll
            for (int i = 0; i < 2; ++i)
#pragma unroll
                for (int j = 0; j < 4; ++j) {
                    mma16(acc_u[i][j], af[i], uf[j]);
                    mma16(acc_g[i][j], af[i], gf[j]);
                }
        }
    }
#undef ISSUE_F

    // epilogue: h = up*silu(gate) -> fp16
#pragma unroll
    for (int i = 0; i < 2; ++i) {
#pragma unroll
        for (int h = 0; h < 2; ++h) {
            const int gm = m0 + wm * 32 + i * 16 + g + h * 8;
            __half* rowp = g_h + (size_t)gm * I_DIM;
#pragma unroll
            for (int j = 0; j < 4; ++j) {
                const int gn = n0 + wn * 32 + j * 8 + 2 * c;
                float u0 = acc_u[i][j][h * 2 + 0], u1 = acc_u[i][j][h * 2 + 1];
                float gg0 = acc_g[i][j][h * 2 + 0], gg1 = acc_g[i][j][h * 2 + 1];
                float h0 = u0 * (gg0 / (1.f + __expf(-gg0)));
                float h1 = u1 * (gg1 / (1.f + __expf(-gg1)));
                *(__half2*)(rowp + gn) = __floats2half2_rn(h0, h1);
            }
        }
    }
}

// ---------------------------------------------------------------------------
// Down half-K tile: 128x128 x K=5504, 16 warps @ 32x32, atomicAdd epilogue.
// ---------------------------------------------------------------------------
__device__ __noinline__ void down_item(int did, float* __restrict__ out) {
    const int Mc = g_count;
    const int k = did & 1;
    const int n = (did >> 1) & 31;
    const int m = did >> 6;
    const int m0 = m * 128;
    if (m0 >= Mc) return;
    const int n0 = n * 128;
    const int k_base = k * I_HALF;
    const int tid = threadIdx.x;

    extern __shared__ __half smh[];
    const uint32_t smem_b = (uint32_t)__cvta_generic_to_shared(smh);

    const int lane = tid & 31;
    const int wid  = tid >> 5;
    const int wm   = wid >> 2;
    const int wn   = wid & 3;
    const int g    = lane >> 2;
    const int c    = lane & 3;
    const int skew = wid & 3;
    const int nk   = I_HALF / BKH;  // 86

    uint32_t a_off[2], b_off[2];
    {
        const int ar = wm * 32 + ((lane >> 3) & 1) * 8 + (lane & 7);
        const int ac = ((lane >> 4) & 1) * 8;
#pragma unroll
        for (int i = 0; i < 2; ++i) a_off[i] = (uint32_t)((ar + i * 16) * LDSTR + ac);
        const int br = wn * 32 + ((lane >> 4) & 1) * 8 + (lane & 7);
        const int bc = ((lane >> 3) & 1) * 8;
#pragma unroll
        for (int p = 0; p < 2; ++p)
            b_off[p] = (uint32_t)(TILE128 + (br + p * 16) * LDSTR + bc);
    }

    const __half* srcA = g_h  + (size_t)m0 * I_DIM + k_base;
    const __half* srcB = g_wd + (size_t)n0 * I_DIM + k_base;

#define ISSUE_D(t) do {                                                        \
        __half* st = smh + ((t) % S) * STG_D;                                  \
        const size_t kof = (size_t)(t) * BKH;                                  \
        _Pragma("unroll")                                                      \
        for (int ii = 0; ii < 2; ++ii) {                                       \
            int id = tid + ii * 512;                                           \
            int row = id >> 3, ch = id & 7;                                    \
            cp16(st + row * LDSTR + ch * 8,                                    \
                 srcA + (size_t)row * I_DIM + kof + ch * 8);                   \
            cp16(st + TILE128 + row * LDSTR + ch * 8,                          \
                 srcB + (size_t)row * I_DIM + kof + ch * 8);                   \
        }                                                                      \
    } while (0)

#pragma unroll
    for (int t = 0; t < S - 1; ++t) { ISSUE_D(t); CP_COMMIT(); }

    float acc[2][4][4];
#pragma unroll
    for (int i = 0; i < 2; ++i)
#pragma unroll
        for (int j = 0; j < 4; ++j)
#pragma unroll
            for (int r = 0; r < 4; ++r) acc[i][j][r] = 0.f;

    for (int t = 0; t < nk; ++t) {
        CP_WAIT(S - 2);
        __syncthreads();
        if (t + S - 1 < nk) ISSUE_D(t + S - 1);
        CP_COMMIT();

        const uint32_t sb = smem_b + (uint32_t)((t % S) * STG_D) * 2;

#pragma unroll
        for (int kgi = 0; kgi < 4; ++kgi) {
            const int kg = (kgi + skew) & 3;
            const uint32_t kb = (uint32_t)kg * 32;
            uint32_t af[2][4], bf[4][2];
#pragma unroll
            for (int i = 0; i < 2; ++i) ldsm4(sb + 2 * a_off[i] + kb, af[i]);
#pragma unroll
            for (int p = 0; p < 2; ++p) {
                uint32_t rb[4];
                ldsm4(sb + 2 * b_off[p] + kb, rb);
                bf[2 * p][0] = rb[0]; bf[2 * p][1] = rb[1];
                bf[2 * p + 1][0] = rb[2]; bf[2 * p + 1][1] = rb[3];
            }
#pragma unroll
            for (int i = 0; i < 2; ++i)
#pragma unroll
                for (int j = 0; j < 4; ++j)
                    mma16(acc[i][j], af[i], bf[j]);
        }
    }
#undef ISSUE_D

    // epilogue: accumulate into out (2 commutative addends -> deterministic)
#pragma unroll
    for (int i = 0; i < 2; ++i) {
#pragma unroll
        for (int h = 0; h < 2; ++h) {
            const int gm = m0 + wm * 32 + i * 16 + g + h * 8;
            if (gm < Mc) {
                float* rowp = out + (size_t)g_idx[gm] * H_DIM;
#pragma unroll
                for (int j = 0; j < 4; ++j) {
                    const int gn = n0 + wn * 32 + j * 8 + 2 * c;
                    atomicAdd(rowp + gn,     acc[i][j][h * 2 + 0]);
                    atomicAdd(rowp + gn + 1, acc[i][j][h * 2 + 1]);
                }
            }
        }
    }
}

// ---------------------------------------------------------------------------
// Persistent mega-kernel
// ---------------------------------------------------------------------------
__global__ __launch_bounds__(NTHREADS, 1)
void mega_kernel(const float4* __restrict__ hidden,
                 const float4* __restrict__ w_up,
                 const float4* __restrict__ w_gate,
                 const float4* __restrict__ w_down,
                 float* __restrict__ out)
{
    __shared__ int s_id;
    const int tid = threadIdx.x;

    // ---- pool 1 ----
    for (;;) {
        __syncthreads();
        if (tid == 0) s_id = atomicAdd(&g_ctl.ctr1, 1);
        __syncthreads();
        const int id = s_id;
        if (id >= TOTAL1) break;
        if (id < ID_CVTW)       gather_item(id, hidden);
        else if (id < ID_FUSED) cvtw_item(id - ID_CVTW, w_up, w_gate);
        else if (id < ID_CVTD)  fused_item(id - ID_FUSED);
        else if (id < ID_ZERO)  cvtd_item(id - ID_CVTD, w_down);
        else                    zero_item(id - ID_ZERO, out);
    }

    // ---- grid barrier (148 co-resident CTAs) ----
    __threadfence();
    __syncthreads();
    if (tid == 0) {
        atomicAdd(&g_ctl.bar, 1);
        while (*(volatile int*)&g_ctl.bar < NCTA) {}
    }
    __syncthreads();
    __threadfence();

    // ---- pool 2: down tiles ----
    for (;;) {
        __syncthreads();
        if (tid == 0) s_id = atomicAdd(&g_ctl.ctr2, 1);
        __syncthreads();
        const int id = s_id;
        if (id >= TOTAL2) return;
        down_item(id, out);
    }
}

// ---------------------------------------------------------------------------
extern "C" void kernel_launch(void* const* d_in, const int* in_sizes, int n_in,
                              void* d_out, int out_size)
{
    const float* hidden = (const float*)d_in[0];
    const float* w_up   = (const float*)d_in[1];
    const float* w_gate = (const float*)d_in[2];
    const float* w_down = (const float*)d_in[3];
    const int*   mask   = (const int*)d_in[4];
    float* out = (float*)d_out;

    cudaFuncSetAttribute(mega_kernel, cudaFuncAttributeMaxDynamicSharedMemorySize, SMEM_BYTES);

    void* ctl_ptr;
    cudaGetSymbolAddress(&ctl_ptr, g_ctl);

    compact_kernel<<<1, 1024>>>(mask);
    cudaMemsetAsync(ctl_ptr, 0, sizeof(Ctl), 0);
    mega_kernel<<<NCTA, NTHREADS, SMEM_BYTES>>>(
        (const float4*)hidden, (const float4*)w_up, (const float4*)w_gate,
        (const float4*)w_down, out);
}

// round 17
// speedup vs baseline: 1.1523x; 1.1523x over previous
#include <cuda_runtime.h>
#include <cuda_fp16.h>
#include <cstdint>
#include <math.h>

// Problem dims (fixed)
#define H_DIM 4096
#define I_DIM 11008
#define NTOK  4096

#define BKH 64                          // halves (k) per pipeline stage
#define S  4
#define LDSTR 72                        // halves per smem row (128B data + 16B pad)
#define TILE128 (128 * LDSTR)
#define TILE256 (256 * LDSTR)
#define NTHREADS 512

// n-quarter boundaries in 128-blocks: sizes 22,22,21,21 (sum 86)
__host__ __device__ __forceinline__ int qb(int q) {
    const int t[5] = {0, 22, 44, 65, 86};
    return t[q];
}

// Device scratch — natural K-major fp16 layouts
__device__ __half g_x[(size_t)NTOK * H_DIM];
__device__ __half g_h[(size_t)NTOK * I_DIM];
__device__ __half g_wu[(size_t)I_DIM * H_DIM];
__device__ __half g_wg[(size_t)I_DIM * H_DIM];
__device__ __half g_wd[(size_t)H_DIM * I_DIM];
__device__ int    g_idx[NTOK];
__device__ int    g_zidx[NTOK];
__device__ int    g_count;

// ---------------------------------------------------------------------------
// Streams + events (host-side only, created once at static init)
// ---------------------------------------------------------------------------
struct AuxStreams {
    cudaStream_t side, fq[4];
    cudaEvent_t ev_fork, ev_G, ev_C[4], ev_F[4], ev_S;
    AuxStreams() {
        cudaStreamCreateWithFlags(&side, cudaStreamNonBlocking);
        for (int i = 0; i < 4; ++i) cudaStreamCreateWithFlags(&fq[i], cudaStreamNonBlocking);
        cudaEventCreateWithFlags(&ev_fork, cudaEventDisableTiming);
        cudaEventCreateWithFlags(&ev_G, cudaEventDisableTiming);
        for (int i = 0; i < 4; ++i) cudaEventCreateWithFlags(&ev_C[i], cudaEventDisableTiming);
        for (int i = 0; i < 4; ++i) cudaEventCreateWithFlags(&ev_F[i], cudaEventDisableTiming);
        cudaEventCreateWithFlags(&ev_S, cudaEventDisableTiming);
    }
};
static AuxStreams g_aux;

// ---------------------------------------------------------------------------
__device__ __forceinline__ uint32_t h2_as_u32(__half2 h) {
    return *reinterpret_cast<uint32_t*>(&h);
}
__device__ __forceinline__ void cp16(void* dst_smem, const void* src) {
    uint32_t d = (uint32_t)__cvta_generic_to_shared(dst_smem);
    asm volatile("cp.async.cg.shared.global [%0], [%1], 16;" :: "r"(d), "l"(src) : "memory");
}
#define CP_COMMIT() asm volatile("cp.async.commit_group;" ::: "memory")
#define CP_WAIT(n)  asm volatile("cp.async.wait_group %0;" :: "n"(n) : "memory")

__device__ __forceinline__ void mma16(float* d, const uint32_t* a, const uint32_t* b) {
    asm volatile(
        "mma.sync.aligned.m16n8k16.row.col.f32.f16.f16.f32 "
        "{%0,%1,%2,%3}, {%4,%5,%6,%7}, {%8,%9}, {%0,%1,%2,%3};"
        : "+f"(d[0]), "+f"(d[1]), "+f"(d[2]), "+f"(d[3])
        : "r"(a[0]), "r"(a[1]), "r"(a[2]), "r"(a[3]), "r"(b[0]), "r"(b[1]));
}
__device__ __forceinline__ void ldsm4(uint32_t addr, uint32_t* r) {
    asm volatile("ldmatrix.sync.aligned.m8n8.x4.shared.b16 {%0,%1,%2,%3}, [%4];"
                 : "=r"(r[0]), "=r"(r[1]), "=r"(r[2]), "=r"(r[3]) : "r"(addr));
}

// ---------------------------------------------------------------------------
// Compaction scan (single block): active list + inactive list
// ---------------------------------------------------------------------------
__global__ void compact_kernel(const int* __restrict__ mask) {
    __shared__ int warp_sums[32];
    const int tid = threadIdx.x, lane = tid & 31, warp = tid >> 5;
    int flags[4], cnt = 0;
#pragma unroll
    for (int j = 0; j < 4; ++j) {
        int f = (mask[tid * 4 + j] != 0) ? 1 : 0;
        flags[j] = f; cnt += f;
    }
    int v = cnt;
#pragma unroll
    for (int o = 1; o < 32; o <<= 1) { int n = __shfl_up_sync(~0u, v, o); if (lane >= o) v += n; }
    if (lane == 31) warp_sums[warp] = v;
    __syncthreads();
    if (warp == 0) {
        int s = warp_sums[lane];
#pragma unroll
        for (int o = 1; o < 32; o <<= 1) { int n = __shfl_up_sync(~0u, s, o); if (lane >= o) s += n; }
        warp_sums[lane] = s;
    }
    __syncthreads();
    int base = v - cnt + (warp > 0 ? warp_sums[warp - 1] : 0);
#pragma unroll
    for (int j = 0; j < 4; ++j) {
        int t = tid * 4 + j;
        if (flags[j]) g_idx[base++] = t;
        else          g_zidx[t - base] = t;
    }
    if (tid == 1023) g_count = base;
}

// ---------------------------------------------------------------------------
__device__ __forceinline__ uint4 cvt8(float4 f0, float4 f1) {
    uint4 o;
    o.x = h2_as_u32(__floats2half2_rn(f0.x, f0.y));
    o.y = h2_as_u32(__floats2half2_rn(f0.z, f0.w));
    o.z = h2_as_u32(__floats2half2_rn(f1.x, f1.y));
    o.w = h2_as_u32(__floats2half2_rn(f1.z, f1.w));
    return o;
}

__global__ void cvt_kernel(const float4* __restrict__ src, uint4* __restrict__ dst, int ngroups) {
    int i = blockIdx.x * blockDim.x + threadIdx.x;
    int stride = gridDim.x * blockDim.x;
    for (; i < ngroups; i += stride) dst[i] = cvt8(src[2 * i], src[2 * i + 1]);
}

// Gather active rows into g_x (fp16); zero-pad to 128-row boundary.
__global__ void gather_kernel(const float4* __restrict__ hidden) {
    int row = blockIdx.x;
    int c = g_count;
    int cpad = (c + 127) & ~127;
    if (row >= cpad) return;
    uint4* dst = (uint4*)(g_x + (size_t)row * H_DIM);
    if (row < c) {
        const float4* src = hidden + (size_t)g_idx[row] * (H_DIM / 4);
        for (int i = threadIdx.x; i < H_DIM / 8; i += 256)
            dst[i] = cvt8(src[2 * i], src[2 * i + 1]);
    } else {
        uint4 z = make_uint4(0, 0, 0, 0);
        for (int i = threadIdx.x; i < H_DIM / 8; i += 256) dst[i] = z;
    }
}

__global__ void zero_rows_kernel(float4* __restrict__ out) {
    int nz = NTOK - g_count;
    if ((int)blockIdx.x >= nz) return;
    float4* p = out + (size_t)g_zidx[blockIdx.x] * (H_DIM / 4);
    float4 z = make_float4(0.f, 0.f, 0.f, 0.f);
    for (int i = threadIdx.x; i < H_DIM / 4; i += 256) p[i] = z;
}

// ---------------------------------------------------------------------------
// Fused up+gate GEMM. Block 128x128, 16 warps @ 32x32 (4m x 4n), dual acc,
// per-warp kg skew. n_off selects the n-quarter (in 128-blocks).
// ---------------------------------------------------------------------------
#define STG_F (3 * TILE128)   // halves per stage

__global__ __launch_bounds__(NTHREADS, 1)
void fused_upgate_kernel(int n_off)
{
    const int Mc = g_count;
    const int m0 = blockIdx.x * 128;
    if (m0 >= Mc) return;
    const int n0 = (blockIdx.y + n_off) * 128;

    extern __shared__ __half smh[];
    const uint32_t smem_b = (uint32_t)__cvta_generic_to_shared(smh);

    const int tid  = threadIdx.x;
    const int lane = tid & 31;
    const int wid  = tid >> 5;      // 0..15
    const int wm   = wid >> 2;      // 0..3
    const int wn   = wid & 3;       // 0..3
    const int g    = lane >> 2;
    const int c    = lane & 3;
    const int skew = wid & 3;

    const int nk = H_DIM / BKH;     // 64

    uint32_t a_off[2], u_off[2], gg_off[2];
    {
        const int ar = wm * 32 + ((lane >> 3) & 1) * 8 + (lane & 7);
        const int ac = ((lane >> 4) & 1) * 8;
#pragma unroll
        for (int i = 0; i < 2; ++i) a_off[i] = (uint32_t)((ar + i * 16) * LDSTR + ac);
        const int br = wn * 32 + ((lane >> 4) & 1) * 8 + (lane & 7);
        const int bc = ((lane >> 3) & 1) * 8;
#pragma unroll
        for (int p = 0; p < 2; ++p) {
            u_off[p]  = (uint32_t)(TILE128     + (br + p * 16) * LDSTR + bc);
            gg_off[p] = (uint32_t)(2 * TILE128 + (br + p * 16) * LDSTR + bc);
        }
    }

    const __half* srcA = g_x  + (size_t)m0 * H_DIM;
    const __half* srcU = g_wu + (size_t)n0 * H_DIM;
    const __half* srcG = g_wg + (size_t)n0 * H_DIM;

#define ISSUE_F(t) do {                                                        \
        __half* st = smh + ((t) % S) * STG_F;                                  \
        const size_t kof = (size_t)(t) * BKH;                                  \
        _Pragma("unroll")                                                      \
        for (int ii = 0; ii < 2; ++ii) {                                       \
            int id = tid + ii * 512;                                           \
            int row = id >> 3, ch = id & 7;                                    \
            cp16(st + row * LDSTR + ch * 8,                                    \
                 srcA + (size_t)row * H_DIM + kof + ch * 8);                   \
            cp16(st + TILE128 + row * LDSTR + ch * 8,                          \
                 srcU + (size_t)row * H_DIM + kof + ch * 8);                   \
            cp16(st + 2 * TILE128 + row * LDSTR + ch * 8,                      \
                 srcG + (size_t)row * H_DIM + kof + ch * 8);                   \
        }                                                                      \
    } while (0)

#pragma unroll
    for (int t = 0; t < S - 1; ++t) { ISSUE_F(t); CP_COMMIT(); }

    float acc_u[2][4][4], acc_g[2][4][4];
#pragma unroll
    for (int i = 0; i < 2; ++i)
#pragma unroll
        for (int j = 0; j < 4; ++j)
#pragma unroll
            for (int r = 0; r < 4; ++r) { acc_u[i][j][r] = 0.f; acc_g[i][j][r] = 0.f; }

    for (int t = 0; t < nk; ++t) {
        CP_WAIT(S - 2);
        __syncthreads();
        if (t + S - 1 < nk) ISSUE_F(t + S - 1);
        CP_COMMIT();

        const uint32_t sb = smem_b + (uint32_t)((t % S) * STG_F) * 2;

#pragma unroll
        for (int kgi = 0; kgi < 4; ++kgi) {
            const int kg = (kgi + skew) & 3;
            const uint32_t kb = (uint32_t)kg * 32;
            uint32_t af[2][4], uf[4][2], gf[4][2];
#pragma unroll
            for (int i = 0; i < 2; ++i) ldsm4(sb + 2 * a_off[i] + kb, af[i]);
#pragma unroll
            for (int p = 0; p < 2; ++p) {
                uint32_t ru[4], rg[4];
                ldsm4(sb + 2 * u_off[p] + kb, ru);
                ldsm4(sb + 2 * gg_off[p] + kb, rg);
                uf[2 * p][0] = ru[0]; uf[2 * p][1] = ru[1];
                uf[2 * p + 1][0] = ru[2]; uf[2 * p + 1][1] = ru[3];
                gf[2 * p][0] = rg[0]; gf[2 * p][1] = rg[1];
                gf[2 * p + 1][0] = rg[2]; gf[2 * p + 1][1] = rg[3];
            }
#pragma unroll
            for (int i = 0; i < 2; ++i)
#pragma unroll
                for (int j = 0; j < 4; ++j) {
                    mma16(acc_u[i][j], af[i], uf[j]);
                    mma16(acc_g[i][j], af[i], gf[j]);
                }
        }
    }
#undef ISSUE_F

    // epilogue: h = up*silu(gate) -> fp16
#pragma unroll
    for (int i = 0; i < 2; ++i) {
#pragma unroll
        for (int h = 0; h < 2; ++h) {
            const int gm = m0 + wm * 32 + i * 16 + g + h * 8;
            __half* rowp = g_h + (size_t)gm * I_DIM;
#pragma unroll
            for (int j = 0; j < 4; ++j) {
                const int gn = n0 + wn * 32 + j * 8 + 2 * c;
                float u0 = acc_u[i][j][h * 2 + 0], u1 = acc_u[i][j][h * 2 + 1];
                float gg0 = acc_g[i][j][h * 2 + 0], gg1 = acc_g[i][j][h * 2 + 1];
                float h0 = u0 * (gg0 / (1.f + __expf(-gg0)));
                float h1 = u1 * (gg1 / (1.f + __expf(-gg1)));
                *(__half2*)(rowp + gn) = __floats2half2_rn(h0, h1);
            }
        }
    }
}

// ---------------------------------------------------------------------------
// Down GEMM, split-K. Block 256x128, 16 warps @ 64x32 (4m x 4n), kg skew.
// k_base/nk select the K chunk; ACC=0 writes out, ACC=1 accumulates.
// ---------------------------------------------------------------------------
#define STG_D (TILE256 + TILE128)

template <int ACC>
__global__ __launch_bounds__(NTHREADS, 1)
void down_kernel(float* __restrict__ out, int k_base, int nk)
{
    const int Mc = g_count;
    const int m0 = blockIdx.x * 256;
    if (m0 >= Mc) return;
    const int n0 = blockIdx.y * 128;

    extern __shared__ __half smh[];
    const uint32_t smem_b = (uint32_t)__cvta_generic_to_shared(smh);

    const int tid  = threadIdx.x;
    const int lane = tid & 31;
    const int wid  = tid >> 5;
    const int wm   = wid >> 2;      // 0..3
    const int wn   = wid & 3;       // 0..3
    const int g    = lane >> 2;
    const int c    = lane & 3;
    const int skew = wid & 3;

    uint32_t a_off[4], b_off[2];
    {
        const int ar = wm * 64 + ((lane >> 3) & 1) * 8 + (lane & 7);
        const int ac = ((lane >> 4) & 1) * 8;
#pragma unroll
        for (int i = 0; i < 4; ++i) a_off[i] = (uint32_t)((ar + i * 16) * LDSTR + ac);
        const int br = wn * 32 + ((lane >> 4) & 1) * 8 + (lane & 7);
        const int bc = ((lane >> 3) & 1) * 8;
#pragma unroll
        for (int p = 0; p < 2; ++p)
            b_off[p] = (uint32_t)(TILE256 + (br + p * 16) * LDSTR + bc);
    }

    const __half* srcA = g_h  + (size_t)m0 * I_DIM + k_base;
    const __half* srcB = g_wd + (size_t)n0 * I_DIM + k_base;

#define ISSUE_D(t) do {                                                        \
        __half* st = smh + ((t) % S) * STG_D;                                  \
        const size_t kof = (size_t)(t) * BKH;                                  \
        _Pragma("unroll")                                                      \
        for (int ii = 0; ii < 4; ++ii) {                                       \
            int id = tid + ii * 512;                                           \
            int row = id >> 3, ch = id & 7;                                    \
            cp16(st + row * LDSTR + ch * 8,                                    \
                 srcA + (size_t)row * I_DIM + kof + ch * 8);                   \
        }                                                                      \
        _Pragma("unroll")                                                      \
        for (int ii = 0; ii < 2; ++ii) {                                       \
            int id = tid + ii * 512;                                           \
            int row = id >> 3, ch = id & 7;                                    \
            cp16(st + TILE256 + row * LDSTR + ch * 8,                          \
                 srcB + (size_t)row * I_DIM + kof + ch * 8);                   \
        }                                                                      \
    } while (0)

#pragma unroll
    for (int t = 0; t < S - 1; ++t) { ISSUE_D(t); CP_COMMIT(); }

    float acc[4][4][4];
#pragma unroll
    for (int i = 0; i < 4; ++i)
#pragma unroll
        for (int j = 0; j < 4; ++j)
#pragma unroll
            for (int r = 0; r < 4; ++r) acc[i][j][r] = 0.f;

    for (int t = 0; t < nk; ++t) {
        CP_WAIT(S - 2);
        __syncthreads();
        if (t + S - 1 < nk) ISSUE_D(t + S - 1);
        CP_COMMIT();

        const uint32_t sb = smem_b + (uint32_t)((t % S) * STG_D) * 2;

#pragma unroll
        for (int kgi = 0; kgi < 4; ++kgi) {
            const int kg = (kgi + skew) & 3;
            const uint32_t kb = (uint32_t)kg * 32;
            uint32_t af[4][4], bf[4][2];
#pragma unroll
            for (int i = 0; i < 4; ++i) ldsm4(sb + 2 * a_off[i] + kb, af[i]);
#pragma unroll
            for (int p = 0; p < 2; ++p) {
                uint32_t rb[4];
                ldsm4(sb + 2 * b_off[p] + kb, rb);
                bf[2 * p][0] = rb[0]; bf[2 * p][1] = rb[1];
                bf[2 * p + 1][0] = rb[2]; bf[2 * p + 1][1] = rb[3];
            }
#pragma unroll
            for (int i = 0; i < 4; ++i)
#pragma unroll
                for (int j = 0; j < 4; ++j)
                    mma16(acc[i][j], af[i], bf[j]);
        }
    }
#undef ISSUE_D

    // epilogue: scatter (write or accumulate)
#pragma unroll
    for (int i = 0; i < 4; ++i) {
#pragma unroll
        for (int h = 0; h < 2; ++h) {
            const int gm = m0 + wm * 64 + i * 16 + g + h * 8;
            if (gm < Mc) {
                float* rowp = out + (size_t)g_idx[gm] * H_DIM;
#pragma unroll
                for (int j = 0; j < 4; ++j) {
                    const int gn = n0 + wn * 32 + j * 8 + c * 2;
                    float2 v = make_float2(acc[i][j][h * 2 + 0], acc[i][j][h * 2 + 1]);
                    if (ACC) {
                        float2 prev = *(float2*)(rowp + gn);
                        v.x += prev.x; v.y += prev.y;
                    }
                    *(float2*)(rowp + gn) = v;
                }
            }
        }
    }
}

// ---------------------------------------------------------------------------
extern "C" void kernel_launch(void* const* d_in, const int* in_sizes, int n_in,
                              void* d_out, int out_size)
{
    const float* hidden = (const float*)d_in[0];
    const float* w_up   = (const float*)d_in[1];
    const float* w_gate = (const float*)d_in[2];
    const float* w_down = (const float*)d_in[3];
    const int*   mask   = (const int*)d_in[4];
    float* out = (float*)d_out;

    const int SMEM_F = S * STG_F * sizeof(__half);   // 221184
    const int SMEM_D = S * STG_D * sizeof(__half);   // 221184
    cudaFuncSetAttribute(fused_upgate_kernel, cudaFuncAttributeMaxDynamicSharedMemorySize, SMEM_F);
    cudaFuncSetAttribute(down_kernel<0>,      cudaFuncAttributeMaxDynamicSharedMemorySize, SMEM_D);
    cudaFuncSetAttribute(down_kernel<1>,      cudaFuncAttributeMaxDynamicSharedMemorySize, SMEM_D);

    void *d_wu, *d_wg, *d_wd;
    cudaGetSymbolAddress(&d_wu, g_wu);
    cudaGetSymbolAddress(&d_wg, g_wg);
    cudaGetSymbolAddress(&d_wd, g_wd);

    const int wd_groups = (I_DIM * H_DIM) / 8;
    dim3 blk(NTHREADS);

    // ---- main: compact, then fork side stream ----
    compact_kernel<<<1, 1024>>>(mask);
    cudaEventRecord(g_aux.ev_fork, 0);
    cudaStreamWaitEvent(g_aux.side, g_aux.ev_fork, 0);

    // ---- side: quarter-staged weight conversion ----
    for (int q = 0; q < 4; ++q) {
        const size_t row0 = (size_t)qb(q) * 128;
        const size_t rows = (size_t)(qb(q + 1) - qb(q)) * 128;
        const size_t f_off = row0 * H_DIM;
        const int groups = (int)(rows * H_DIM / 8);
        cvt_kernel<<<2048, 256, 0, g_aux.side>>>(
            (const float4*)(w_up + f_off), (uint4*)((__half*)d_wu + f_off), groups);
        cvt_kernel<<<2048, 256, 0, g_aux.side>>>(
            (const float4*)(w_gate + f_off), (uint4*)((__half*)d_wg + f_off), groups);
        cudaEventRecord(g_aux.ev_C[q], g_aux.side);
    }
    cvt_kernel<<<4096, 256, 0, g_aux.side>>>((const float4*)w_down, (uint4*)d_wd, wd_groups);
    zero_rows_kernel<<<NTOK, 256, 0, g_aux.side>>>((float4*)out);

    // ---- main: gather ----
    gather_kernel<<<NTOK, 256>>>((const float4*)hidden);
    cudaEventRecord(g_aux.ev_G, 0);

    // ---- fused quarters on separate streams (tails overlap) ----
    for (int q = 0; q < 4; ++q) {
        cudaStreamWaitEvent(g_aux.fq[q], g_aux.ev_G, 0);
        cudaStreamWaitEvent(g_aux.fq[q], g_aux.ev_C[q], 0);
        fused_upgate_kernel<<<dim3(NTOK / 128, qb(q + 1) - qb(q)), blk, SMEM_F, g_aux.fq[q]>>>(qb(q));
        cudaEventRecord(g_aux.ev_F[q], g_aux.fq[q]);
    }

    // ---- side: down chunks 0..2 (sequential, deterministic accumulate) ----
    for (int q = 0; q < 3; ++q) {
        cudaStreamWaitEvent(g_aux.side, g_aux.ev_F[q], 0);
        const int k_base = qb(q) * 128;
        const int nk = (qb(q + 1) - qb(q)) * 2;   // *128/64
        if (q == 0)
            down_kernel<0><<<dim3(NTOK / 256, H_DIM / 128), blk, SMEM_D, g_aux.side>>>(out, k_base, nk);
        else
            down_kernel<1><<<dim3(NTOK / 256, H_DIM / 128), blk, SMEM_D, g_aux.side>>>(out, k_base, nk);
    }
    cudaEventRecord(g_aux.ev_S, g_aux.side);

    // ---- main: final down chunk after last fused + side chunks ----
    cudaStreamWaitEvent(0, g_aux.ev_F[3], 0);
    cudaStreamWaitEvent(0, g_aux.ev_S, 0);
    down_kernel<1><<<dim3(NTOK / 256, H_DIM / 128), blk, SMEM_D>>>(out, qb(3) * 128, (qb(4) - qb(3)) * 2);
}